// round 6
// baseline (speedup 1.0000x reference)
#include <cuda_runtime.h>
#include <cuda_bf16.h>
#include <cstdint>

#define Bx   16
#define Nn   1024
#define DINc 128
#define Hh   4
#define Dd   32
#define HD   128
#define BN   (Bx*Nn)
#define LOG2E 1.4426950408889634f

// ---------------------------------------------------------------------------
// Scratch (device globals — no allocation allowed in kernel_launch)
// ---------------------------------------------------------------------------
__device__ float    g_hT[(size_t)Bx*Hh*Nn*Dd];   // 8.4 MB tf32-rounded, [b][hh][j][d]
__device__ float    g_ei[(size_t)Hh*BN];         // [hh][row], pre-scaled by log2(e)
__device__ float    g_ej[(size_t)Hh*BN];
__device__ unsigned g_am[(size_t)32*BN];         // [jt][row] packed adjacency bits
__device__ float    g_wa[2][Hh][DINc];           // W @ a_{i,j}, pre-scaled by log2(e)
__device__ float    g_ba[2][Hh];                 // b · a_{i,j}, pre-scaled

__device__ __forceinline__ float tf32r(float x) {
    uint32_t u; asm("cvt.rna.tf32.f32 %0, %1;" : "=r"(u) : "f"(x));
    return __uint_as_float(u);
}

// ---------------------------------------------------------------------------
// Kernel 0: one block. wa[s][hh][k] = sum_d W[k][hh*32+d] * a[s*32+d];
//           ba[s][hh] = sum_d b[hh*32+d] * a[s*32+d].  (both * log2e)
// ---------------------------------------------------------------------------
__global__ void __launch_bounds__(128) k_prep(const float* __restrict__ W,
                                              const float* __restrict__ bias,
                                              const float* __restrict__ a) {
    __shared__ float as[64];
    const int k = threadIdx.x;
    if (k < 64) as[k] = a[k];
    __syncthreads();
#pragma unroll
    for (int hh = 0; hh < Hh; hh++) {
        float si = 0.f, sj = 0.f;
#pragma unroll
        for (int d = 0; d < 32; d++) {
            float w = W[k*HD + hh*32 + d];
            si = fmaf(w, as[d],      si);
            sj = fmaf(w, as[32 + d], sj);
        }
        g_wa[0][hh][k] = si * LOG2E;
        g_wa[1][hh][k] = sj * LOG2E;
    }
    if (k < 8) {
        const int s = k >> 2, hh = k & 3;
        float acc = 0.f;
#pragma unroll
        for (int d = 0; d < 32; d++) acc += bias[hh*32 + d] * as[s*32 + d];
        g_ba[s][hh] = acc * LOG2E;
    }
}

// ---------------------------------------------------------------------------
// Kernel 1: h = x@W + b -> g_hT (tf32, [b][hh][j][d]).
// 256 threads, 64 rows/block. W read via LDG (64 KB, L1-resident);
// x tile staged in smem (32 KB). No shuffles, no edge logits here.
// ---------------------------------------------------------------------------
__global__ void __launch_bounds__(256, 2) k_gemm(const float* __restrict__ x,
                                                 const float* __restrict__ W,
                                                 const float* __restrict__ bias) {
    __shared__ float4 xs4[64*32];      // 32 KB (64 rows x 128 floats)
    const int tid = threadIdx.x;
    const int c   = tid & 127;         // output column
    const int rg  = tid >> 7;          // row-group 0/1
    const size_t row0 = (size_t)blockIdx.x * 64;

    const float4* x4 = (const float4*)(x + row0*DINc);
    for (int i = tid; i < 64*32; i += 256) xs4[i] = x4[i];
    __syncthreads();

    float acc[32];
#pragma unroll
    for (int r = 0; r < 32; r++) acc[r] = 0.f;

#pragma unroll 4
    for (int k = 0; k < DINc; k += 4) {
        const float w0 = __ldg(&W[(k+0)*HD + c]);
        const float w1 = __ldg(&W[(k+1)*HD + c]);
        const float w2 = __ldg(&W[(k+2)*HD + c]);
        const float w3 = __ldg(&W[(k+3)*HD + c]);
#pragma unroll
        for (int r = 0; r < 32; r++) {
            float4 xv = xs4[(rg*32 + r)*32 + (k >> 2)];   // broadcast LDS.128
            acc[r] = fmaf(xv.x, w0, fmaf(xv.y, w1, fmaf(xv.z, w2, fmaf(xv.w, w3, acc[r]))));
        }
    }
    const int d  = c & 31, hh = c >> 5;
    const float bc = bias[c];

    const int b  = (int)(row0 >> 10);
    const int jt = (int)(((row0 >> 5) & 31) + rg);
    float* ht = g_hT + (((size_t)b*Hh + hh) << 15) + ((size_t)jt*32 << 5) + d;
#pragma unroll
    for (int r = 0; r < 32; r++) ht[r*32] = tf32r(acc[r] + bc);
}

// ---------------------------------------------------------------------------
// Kernel 2: pack adj bits + edge logits from x (ei = x·wa_i + ba_i).
// One warp per row.
// ---------------------------------------------------------------------------
__global__ void __launch_bounds__(256) k_pack(const int* __restrict__ adj,
                                              const float* __restrict__ x) {
    const int row  = (blockIdx.x*256 + threadIdx.x) >> 5;
    const int lane = threadIdx.x & 31;

    // ---- edge logits
    const float4 xv = ((const float4*)(x + (size_t)row*DINc))[lane];
    float ev[8];
#pragma unroll
    for (int q = 0; q < 8; q++) {
        const float4 wv = *(const float4*)&g_wa[q >> 2][q & 3][lane*4];
        ev[q] = fmaf(xv.x, wv.x, fmaf(xv.y, wv.y, fmaf(xv.z, wv.z, xv.w*wv.w)));
    }
#pragma unroll
    for (int q = 0; q < 8; q++)
#pragma unroll
        for (int o = 16; o > 0; o >>= 1)
            ev[q] += __shfl_xor_sync(0xffffffffu, ev[q], o);
    if (lane == 0) {
#pragma unroll
        for (int q = 0; q < 8; q++) {
            const int s = q >> 2, hh = q & 3;
            float v = ev[q] + g_ba[s][hh];
            (s ? g_ej : g_ei)[(size_t)hh*BN + row] = v;
        }
    }

    // ---- adjacency bit pack, layout [jt-word][row]
    const int* ar = adj + (size_t)row*Nn;
#pragma unroll
    for (int wd = 0; wd < Nn/32; wd++) {
        unsigned mm = __ballot_sync(0xffffffffu, ar[wd*32 + lane] > 0);
        if (lane == 0) g_am[(size_t)wd*BN + row] = mm;
    }
}

// ---------------------------------------------------------------------------
// Kernel 3: flash attention via mma.sync.m16n8k8 tf32.
// Grid (8 i-tiles, Hh, Bx), 128 threads = 4 warps; warp owns 32 i-rows.
// P computed straight into A-fragment registers (no smem for P).
// h tile (32j x 32d) staged in double-buffered smem, one bar.sync per jt.
// ---------------------------------------------------------------------------
__global__ void __launch_bounds__(128) k_attn(float* __restrict__ out) {
    __shared__ float    ejs[Nn];          // 4 KB
    __shared__ unsigned ams[32*128];      // 16 KB  [jt][rlocal]
    __shared__ float    hs[2][32*36];     // 9.2 KB padded [j][d]

    const int tid  = threadIdx.x;
    const int lane = tid & 31;
    const int w    = tid >> 5;
    const int qid  = lane >> 2;           // 0..7
    const int tq   = lane & 3;            // 0..3
    const int hh   = blockIdx.y;
    const int b    = blockIdx.z;
    const int i0   = blockIdx.x * 128;
    const size_t bN = (size_t)b * Nn;

    // stage ej + masks for the whole block
    {
        const float* ejsrc = g_ej + (size_t)hh*BN + bN;
        for (int k = tid; k < Nn; k += 128) ejs[k] = ejsrc[k];
        const unsigned* amsrc = g_am + bN + i0;
        for (int k = tid; k < 32*128; k += 128)
            ams[k] = amsrc[(size_t)(k >> 7)*BN + (k & 127)];
    }

    float eir[4], lden[4];
#pragma unroll
    for (int m = 0; m < 4; m++) {
        eir[m]  = g_ei[(size_t)hh*BN + bN + i0 + w*32 + qid + 8*m];
        lden[m] = 0.f;
    }

    float acc[2][4][4];
#pragma unroll
    for (int mt = 0; mt < 2; mt++)
#pragma unroll
        for (int nt = 0; nt < 4; nt++)
#pragma unroll
            for (int k = 0; k < 4; k++) acc[mt][nt][k] = 0.f;

    const float* htsrc = g_hT + (((size_t)b*Hh + hh) << 15);
    const float4* hsrc4 = (const float4*)htsrc;
    float4 hv0 = hsrc4[tid];
    float4 hv1 = hsrc4[tid + 128];
    __syncthreads();   // ejs/ams visible

    for (int jt = 0; jt < 32; jt++) {
        const int buf = jt & 1;
        // store prefetched h tile (padded rows: j = idx/8, d0 = (idx%8)*4)
        {
            float* hd0 = &hs[buf][(tid >> 3)*36 + (tid & 7)*4];
            float* hd1 = &hs[buf][((tid + 128) >> 3)*36 + (tid & 7)*4];
            *(float4*)hd0 = hv0;
            *(float4*)hd1 = hv1;
        }
        __syncthreads();
        if (jt < 31) {
            const float4* nx = (const float4*)(htsrc + (size_t)(jt + 1)*1024);
            hv0 = nx[tid]; hv1 = nx[tid + 128];
        }

        // ---- phase A: P in A-fragment layout
        const float* ej = ejs + jt*32;
        float ejv[8];
#pragma unroll
        for (int t = 0; t < 8; t++) ejv[t] = ej[tq + 4*t];
        unsigned mw[4];
#pragma unroll
        for (int m = 0; m < 4; m++) mw[m] = ams[jt*128 + w*32 + qid + 8*m];

        uint32_t pu[4][8];
#pragma unroll
        for (int m = 0; m < 4; m++) {
            const float ei = eir[m];
#pragma unroll
            for (int t = 0; t < 8; t++) {
                float e = ei + ejv[t];
                e = fmaxf(e, 0.2f*e);                       // leaky relu (log2-scaled)
                e = ((mw[m] >> (tq + 4*t)) & 1u) ? e : -10000.f;
                float p; asm("ex2.approx.ftz.f32 %0, %1;" : "=f"(p) : "f"(e));
                lden[m] += p;
                asm("cvt.rna.tf32.f32 %0, %1;" : "=r"(pu[m][t]) : "f"(p));
            }
        }

        // ---- phase B: 32 x m16n8k8 tf32 mma
#pragma unroll
        for (int ks = 0; ks < 4; ks++) {
            const float* hrow0 = &hs[buf][(ks*8 + tq)*36 + qid];
            const float* hrow1 = hrow0 + 4*36;
            uint32_t b0[4], b1[4];
#pragma unroll
            for (int nt = 0; nt < 4; nt++) {
                b0[nt] = __float_as_uint(hrow0[nt*8]);
                b1[nt] = __float_as_uint(hrow1[nt*8]);
            }
#pragma unroll
            for (int mt = 0; mt < 2; mt++) {
                const uint32_t a0 = pu[2*mt  ][2*ks  ];
                const uint32_t a1 = pu[2*mt+1][2*ks  ];
                const uint32_t a2 = pu[2*mt  ][2*ks+1];
                const uint32_t a3 = pu[2*mt+1][2*ks+1];
#pragma unroll
                for (int nt = 0; nt < 4; nt++) {
                    asm("mma.sync.aligned.m16n8k8.row.col.f32.tf32.tf32.f32 "
                        "{%0,%1,%2,%3}, {%4,%5,%6,%7}, {%8,%9}, {%0,%1,%2,%3};"
                        : "+f"(acc[mt][nt][0]), "+f"(acc[mt][nt][1]),
                          "+f"(acc[mt][nt][2]), "+f"(acc[mt][nt][3])
                        : "r"(a0), "r"(a1), "r"(a2), "r"(a3),
                          "r"(b0[nt]), "r"(b1[nt]));
                }
            }
        }
    }

    // ---- finish denominators (sum the 4 j-phase lanes) and store
#pragma unroll
    for (int m = 0; m < 4; m++) {
        lden[m] += __shfl_xor_sync(0xffffffffu, lden[m], 1);
        lden[m] += __shfl_xor_sync(0xffffffffu, lden[m], 2);
        lden[m] = 1.f / lden[m];
    }
#pragma unroll
    for (int mt = 0; mt < 2; mt++) {
#pragma unroll
        for (int half = 0; half < 2; half++) {
            const int m = 2*mt + half;
            const int grow = i0 + w*32 + mt*16 + qid + 8*half;
            const float rl = lden[m];
            float* orow = out + (bN + grow)*HD + hh*32 + tq*2;
#pragma unroll
            for (int nt = 0; nt < 4; nt++) {
                float2 v = { acc[mt][nt][half*2 + 0]*rl, acc[mt][nt][half*2 + 1]*rl };
                *(float2*)(orow + nt*8) = v;
            }
        }
    }
}

// ---------------------------------------------------------------------------
extern "C" void kernel_launch(void* const* d_in, const int* in_sizes, int n_in,
                              void* d_out, int out_size) {
    const float* x = nullptr; const int* adj = nullptr;
    const float* W = nullptr; const float* bias = nullptr; const float* a = nullptr;
    for (int i = 0; i < n_in; i++) {
        switch (in_sizes[i]) {
            case Bx*Nn*DINc: x    = (const float*)d_in[i]; break;
            case Bx*Nn*Nn:   adj  = (const int*)  d_in[i]; break;
            case DINc*HD:    W    = (const float*)d_in[i]; break;
            case HD:         bias = (const float*)d_in[i]; break;
            case 2*Dd:       a    = (const float*)d_in[i]; break;
        }
    }
    k_prep<<<1, 128>>>(W, bias, a);
    k_gemm<<<BN/64, 256>>>(x, W, bias);
    k_pack<<<BN/8, 256>>>(adj, x);
    k_attn<<<dim3(8, Hh, Bx), 128>>>((float*)d_out);
}